// round 1
// baseline (speedup 1.0000x reference)
#include <cuda_runtime.h>
#include <math.h>

#define MTOK   16384
#define DIM    1024
#define NCLS   1000
#define NLAYER 6
#define NBR    3
#define SDIM   64
#define KKEEP  204
#define THRESH 0.85f

// ---------------- scratch (no allocation allowed) ----------------
__device__ float  g_x[(size_t)MTOK * DIM];
__device__ float  g_h[(size_t)MTOK * DIM];
__device__ float  g_sims[(size_t)NBR * MTOK * DIM];
__device__ float  g_z[(size_t)MTOK * SDIM];
__device__ float  g_logits[(size_t)MTOK * NCLS];
__device__ double g_vloss;
__device__ double g_scores[NBR];
__device__ int    g_best;
__device__ unsigned long long g_depth;
__device__ unsigned char g_active[MTOK];

// ---------------- init: reset state + copy x ----------------
__global__ void init_k(const float* __restrict__ xin)
{
    size_t i = (size_t)blockIdx.x * blockDim.x + threadIdx.x;
    if (i < MTOK) g_active[i] = 1;
    if (i == 0) {
        g_vloss = 0.0; g_depth = 0ull; g_best = 0;
        g_scores[0] = 0.0; g_scores[1] = 0.0; g_scores[2] = 0.0;
    }
    const size_t n4 = (size_t)MTOK * DIM / 4;
    const float4* src = (const float4*)xin;
    float4* dst = (float4*)g_x;
    for (size_t j = i; j < n4; j += (size_t)gridDim.x * blockDim.x) dst[j] = src[j];
}

// ---------------- generic tiled SGEMM with fused epilogues ----------------
// C[M,N] = epi(A[M,K] @ B[K,N] + bias[N])
// Requirements used here: M % 128 == 0, K % 16 == 0 (true for all calls).
// N may be arbitrary (guarded).
enum { EPI_NONE = 0, EPI_GELU = 1, EPI_RELU = 2, EPI_LOSS = 3 };

#define BM 128
#define BN 128
#define BK 16

template <int EPI>
__global__ __launch_bounds__(256)
void sgemm_k(const float* __restrict__ A, const float* __restrict__ B,
             const float* __restrict__ bias, float* __restrict__ Cout,
             int M, int N, int K,
             const float* __restrict__ Xres, double* __restrict__ lossAcc)
{
    __shared__ float As[BK][BM];
    __shared__ float Bs[BK][BN];
    __shared__ float red[256];

    const int tid = threadIdx.x;
    const int tx = tid & 15;       // 0..15
    const int ty = tid >> 4;       // 0..15
    const int row0 = blockIdx.y * BM;
    const int col0 = blockIdx.x * BN;

    // A loader: thread -> (row = tid/4 + i*64, col = (tid&3)*4), i in {0,1}
    const int a_r = tid >> 2;
    const int a_c = (tid & 3) << 2;
    // B loader: thread -> (row = tid/32 + i*8, col = (tid&31)*4), i in {0,1}
    const int b_r = tid >> 5;
    const int b_c = (tid & 31) << 2;

    float acc[8][8];
#pragma unroll
    for (int i = 0; i < 8; i++)
#pragma unroll
        for (int j = 0; j < 8; j++) acc[i][j] = 0.0f;

    for (int k0 = 0; k0 < K; k0 += BK) {
        // ---- load A tile (always in-bounds; transpose into smem) ----
#pragma unroll
        for (int i = 0; i < 2; i++) {
            const int r = a_r + i * 64;
            const float4 v = *reinterpret_cast<const float4*>(
                &A[(size_t)(row0 + r) * K + k0 + a_c]);
            As[a_c + 0][r] = v.x;
            As[a_c + 1][r] = v.y;
            As[a_c + 2][r] = v.z;
            As[a_c + 3][r] = v.w;
        }
        // ---- load B tile (guard N) ----
#pragma unroll
        for (int i = 0; i < 2; i++) {
            const int r = b_r + i * 8;
            const int gc = col0 + b_c;
            float4 v;
            if (gc + 3 < N) {
                v = *reinterpret_cast<const float4*>(&B[(size_t)(k0 + r) * N + gc]);
            } else {
                v.x = (gc + 0 < N) ? B[(size_t)(k0 + r) * N + gc + 0] : 0.0f;
                v.y = (gc + 1 < N) ? B[(size_t)(k0 + r) * N + gc + 1] : 0.0f;
                v.z = (gc + 2 < N) ? B[(size_t)(k0 + r) * N + gc + 2] : 0.0f;
                v.w = (gc + 3 < N) ? B[(size_t)(k0 + r) * N + gc + 3] : 0.0f;
            }
            *reinterpret_cast<float4*>(&Bs[r][b_c]) = v;
        }
        __syncthreads();

#pragma unroll
        for (int kk = 0; kk < BK; kk++) {
            float a[8], b[8];
#pragma unroll
            for (int i = 0; i < 8; i++) a[i] = As[kk][ty * 8 + i];
#pragma unroll
            for (int j = 0; j < 8; j++) b[j] = Bs[kk][tx * 8 + j];
#pragma unroll
            for (int i = 0; i < 8; i++)
#pragma unroll
                for (int j = 0; j < 8; j++)
                    acc[i][j] = fmaf(a[i], b[j], acc[i][j]);
        }
        __syncthreads();
    }

    // ---- epilogue ----
    float lsum = 0.0f;
#pragma unroll
    for (int i = 0; i < 8; i++) {
        const int gr = row0 + ty * 8 + i;
#pragma unroll
        for (int j = 0; j < 8; j++) {
            const int gc = col0 + tx * 8 + j;
            if (gc < N) {
                float v = acc[i][j] + bias[gc];
                if (EPI == EPI_GELU) v = 0.5f * v * (1.0f + erff(v * 0.70710678118654752f));
                if (EPI == EPI_RELU) v = fmaxf(v, 0.0f);
                if (EPI == EPI_LOSS) {
                    const float d = v - Xres[(size_t)gr * N + gc];
                    lsum += d * d;
                } else {
                    Cout[(size_t)gr * N + gc] = v;
                }
            }
        }
    }
    if (EPI == EPI_LOSS) {
        red[tid] = lsum;
        __syncthreads();
        for (int s = 128; s > 0; s >>= 1) {
            if (tid < s) red[tid] += red[tid + s];
            __syncthreads();
        }
        if (tid == 0) atomicAdd(lossAcc, (double)red[0]);
    }
}

// ---------------- top-K magnitude select + gated residual add ----------------
// Per token (block): find K-th largest |h| via 4x8-bit MSB radix select,
// keep h where |h| >= kth (tie semantics identical to top_k), x += kept if active.
__global__ __launch_bounds__(256)
void topk_k(const float* __restrict__ H, float* __restrict__ X)
{
    const int tok = blockIdx.x;
    const int tid = threadIdx.x;

    __shared__ unsigned int hist[256];
    __shared__ unsigned int sh_prefix;
    __shared__ int sh_k;

    const float* hrow = H + (size_t)tok * DIM;
    float hv[4];
    unsigned int key[4];
#pragma unroll
    for (int i = 0; i < 4; i++) {
        hv[i] = hrow[tid + i * 256];
        key[i] = __float_as_uint(fabsf(hv[i]));  // |f| bits: uint order == float order
    }

    if (tid == 0) { sh_prefix = 0u; sh_k = KKEEP; }
    __syncthreads();

    for (int round = 0; round < 4; round++) {
        const int shift = 24 - round * 8;
        const unsigned int prefix = sh_prefix;
        const int kneed = sh_k;
        const unsigned int mask_hi = (round == 0) ? 0u : (0xFFFFFFFFu << (shift + 8));
        hist[tid] = 0u;
        __syncthreads();
#pragma unroll
        for (int i = 0; i < 4; i++) {
            if ((key[i] & mask_hi) == prefix)
                atomicAdd(&hist[(key[i] >> shift) & 0xFF], 1u);
        }
        __syncthreads();
        if (tid == 0) {
            int cum = 0;
            int b = 255;
            for (; b > 0; b--) {
                const int c = (int)hist[b];
                if (cum + c >= kneed) break;
                cum += c;
            }
            sh_prefix = prefix | ((unsigned int)b << shift);
            sh_k = kneed - cum;
        }
        __syncthreads();
    }
    const unsigned int kth = sh_prefix;

    if (g_active[tok]) {
        float* xrow = X + (size_t)tok * DIM;
#pragma unroll
        for (int i = 0; i < 4; i++) {
            const float add = (key[i] >= kth) ? hv[i] : 0.0f;
            xrow[tid + i * 256] += add;
        }
    }
}

// ---------------- CEN coherence scores ----------------
__global__ __launch_bounds__(256)
void coh_k(const float* __restrict__ cohW, const float* __restrict__ cohB)
{
    const int tok = blockIdx.x;
    const int n = blockIdx.y;
    const int tid = threadIdx.x;
    if (!g_active[tok]) return;

    const float* srow = g_sims + ((size_t)n * MTOK + tok) * DIM;
    float s = 0.0f;
    for (int i = tid; i < DIM; i += 256) s = fmaf(srow[i], cohW[i], s);

    __shared__ float red[256];
    red[tid] = s;
    __syncthreads();
    for (int st = 128; st > 0; st >>= 1) {
        if (tid < st) red[tid] += red[tid + st];
        __syncthreads();
    }
    if (tid == 0) atomicAdd(&g_scores[n], (double)(red[0] + cohB[0]));
}

__global__ void argmax_k()
{
    int b = 0;
    if (g_scores[1] > g_scores[b]) b = 1;
    if (g_scores[2] > g_scores[b]) b = 2;
    g_best = b;
}

__global__ __launch_bounds__(256)
void cen_add_k()
{
    const size_t i4 = (size_t)blockIdx.x * blockDim.x + threadIdx.x;  // float4 idx
    const size_t tok = (i4 * 4) / DIM;
    if (!g_active[tok]) return;
    const float4* s = (const float4*)(g_sims + (size_t)g_best * MTOK * DIM);
    float4* x = (float4*)g_x;
    float4 a = x[i4];
    const float4 b = s[i4];
    a.x += b.x; a.y += b.y; a.z += b.z; a.w += b.w;
    x[i4] = a;
}

// ---------------- exit head: confidence + scatter + active update ----------------
__global__ __launch_bounds__(256)
void exit_k(const float* __restrict__ logits, float* __restrict__ out)
{
    const int tok = blockIdx.x;
    const int tid = threadIdx.x;
    if (!g_active[tok]) return;  // uniform per block

    const float* lrow = logits + (size_t)tok * NCLS;
    __shared__ float red[256];

    float m = -INFINITY;
    for (int c = tid; c < NCLS; c += 256) m = fmaxf(m, lrow[c]);
    red[tid] = m;
    __syncthreads();
    for (int s = 128; s > 0; s >>= 1) {
        if (tid < s) red[tid] = fmaxf(red[tid], red[tid + s]);
        __syncthreads();
    }
    const float gmax = red[0];
    __syncthreads();

    float se = 0.0f;
    for (int c = tid; c < NCLS; c += 256) se += expf(lrow[c] - gmax);
    red[tid] = se;
    __syncthreads();
    for (int s = 128; s > 0; s >>= 1) {
        if (tid < s) red[tid] += red[tid + s];
        __syncthreads();
    }
    const float conf = 1.0f / red[0];  // softmax max = exp(0)/sum(exp(l-gmax))

    // scatter logits to final output (token is active)
    float* orow = out + (size_t)tok * NCLS;
    for (int c = tid; c < NCLS; c += 256) orow[c] = lrow[c];

    if (tid == 0) {
        atomicAdd(&g_depth, 1ull);
        g_active[tok] = (conf < THRESH) ? 1 : 0;
    }
}

// ---------------- finalize scalars ----------------
__global__ void finalize_k(float* __restrict__ out)
{
    out[(size_t)MTOK * NCLS + 0] = (float)((double)g_depth / (double)MTOK);
    out[(size_t)MTOK * NCLS + 1] =
        (float)(g_vloss / ((double)NLAYER * (double)MTOK * (double)DIM));
}

// ---------------- host driver (graph-capturable) ----------------
extern "C" void kernel_launch(void* const* d_in, const int* in_sizes, int n_in,
                              void* d_out, int out_size)
{
    const float* x_in = (const float*)d_in[0];
    const float* dcaW = (const float*)d_in[1];
    const float* dcaB = (const float*)d_in[2];
    const float* exW  = (const float*)d_in[3];
    const float* exB  = (const float*)d_in[4];
    const float* cenW = (const float*)d_in[5];
    const float* cenB = (const float*)d_in[6];
    const float* cohW = (const float*)d_in[7];
    const float* cohB = (const float*)d_in[8];
    const float* encW = (const float*)d_in[9];
    const float* encB = (const float*)d_in[10];
    const float* decW = (const float*)d_in[11];
    const float* decB = (const float*)d_in[12];
    float* out = (float*)d_out;

    float *px, *ph, *psims, *pz, *plog;
    double* pvl;
    cudaGetSymbolAddress((void**)&px, g_x);
    cudaGetSymbolAddress((void**)&ph, g_h);
    cudaGetSymbolAddress((void**)&psims, g_sims);
    cudaGetSymbolAddress((void**)&pz, g_z);
    cudaGetSymbolAddress((void**)&plog, g_logits);
    cudaGetSymbolAddress((void**)&pvl, g_vloss);

    init_k<<<4096, 256>>>(x_in);

    const dim3 blk(256);
    const dim3 grid_full(DIM / BN, MTOK / BM);      // 1024-wide GEMMs
    const dim3 grid_cls((NCLS + BN - 1) / BN, MTOK / BM);
    const dim3 grid_enc(1, MTOK / BM);              // N=64

    for (int i = 0; i < NLAYER; i++) {
        // SparseDCA: h = gelu(x @ W + b)
        sgemm_k<EPI_GELU><<<grid_full, blk>>>(px, dcaW + (size_t)i * DIM * DIM,
                                              dcaB + (size_t)i * DIM, ph,
                                              MTOK, DIM, DIM, nullptr, nullptr);
        // top-K keep + gated residual
        topk_k<<<MTOK, 256>>>(ph, px);

        if (i == NLAYER / 2) {
            for (int n = 0; n < NBR; n++)
                sgemm_k<EPI_GELU><<<grid_full, blk>>>(
                    px, cenW + (size_t)n * DIM * DIM, cenB + (size_t)n * DIM,
                    psims + (size_t)n * MTOK * DIM, MTOK, DIM, DIM, nullptr, nullptr);
            coh_k<<<dim3(MTOK, NBR), 256>>>(cohW, cohB);
            argmax_k<<<1, 1>>>();
            cen_add_k<<<(MTOK * DIM / 4) / 256, 256>>>();
        }

        // VLM: z = relu(x @ encW + encB); loss += sum((z @ decW + decB - x)^2)
        sgemm_k<EPI_RELU><<<grid_enc, blk>>>(px, encW, encB, pz,
                                             MTOK, SDIM, DIM, nullptr, nullptr);
        sgemm_k<EPI_LOSS><<<grid_full, blk>>>(pz, decW, decB, nullptr,
                                              MTOK, DIM, SDIM, px, pvl);

        // exit head logits
        sgemm_k<EPI_NONE><<<grid_cls, blk>>>(px, exW + (size_t)i * DIM * NCLS,
                                             exB + (size_t)i * NCLS, plog,
                                             MTOK, NCLS, DIM, nullptr, nullptr);
        exit_k<<<MTOK, 256>>>(plog, out);
    }

    finalize_k<<<1, 1>>>(out);
}

// round 2
// speedup vs baseline: 1.1570x; 1.1570x over previous
#include <cuda_runtime.h>
#include <math.h>

#define MTOK   16384
#define DIM    1024
#define NCLS   1000
#define NLAYER 6
#define NBR    3
#define SDIM   64
#define KKEEP  204
#define THRESH 0.85f

// ---------------- scratch (no allocation allowed) ----------------
__device__ float  g_x[(size_t)MTOK * DIM];
__device__ float  g_h[(size_t)MTOK * DIM];
__device__ float  g_sims[(size_t)NBR * MTOK * DIM];
__device__ float  g_z[(size_t)MTOK * SDIM];
__device__ float  g_logits[(size_t)MTOK * NCLS];
__device__ double g_vloss;
__device__ double g_scores[NBR];
__device__ int    g_best;
__device__ unsigned long long g_depth;
__device__ unsigned char g_active[MTOK];

// ---------------- small asm helpers ----------------
__device__ __forceinline__ unsigned sptr(const void* p) {
    return (unsigned)__cvta_generic_to_shared(p);
}
__device__ __forceinline__ void cpa16(unsigned d, const float* s) {
    asm volatile("cp.async.cg.shared.global [%0], [%1], 16;" :: "r"(d), "l"(s));
}
__device__ __forceinline__ void cpa16z(unsigned d, const float* s, int n) {
    asm volatile("cp.async.cg.shared.global [%0], [%1], 16, %2;" :: "r"(d), "l"(s), "r"(n));
}
__device__ __forceinline__ unsigned long long pk(float lo, float hi) {
    unsigned long long r;
    asm("mov.b64 %0, {%1, %2};" : "=l"(r) : "f"(lo), "f"(hi));
    return r;
}
__device__ __forceinline__ void upk(unsigned long long v, float& lo, float& hi) {
    asm("mov.b64 {%0, %1}, %2;" : "=f"(lo), "=f"(hi) : "l"(v));
}
// packed fp32 FMA (SASS FFMA2) — bitwise-identical IEEE fp32 per lane
__device__ __forceinline__ void ffma2(unsigned long long& c, unsigned long long a,
                                      unsigned long long b) {
    asm("fma.rn.f32x2 %0, %1, %2, %0;" : "+l"(c) : "l"(a), "l"(b));
}

// ---------------- init: reset state + copy x ----------------
__global__ void init_k(const float* __restrict__ xin)
{
    size_t i = (size_t)blockIdx.x * blockDim.x + threadIdx.x;
    if (i < MTOK) g_active[i] = 1;
    if (i == 0) {
        g_vloss = 0.0; g_depth = 0ull; g_best = 0;
        g_scores[0] = 0.0; g_scores[1] = 0.0; g_scores[2] = 0.0;
    }
    const size_t n4 = (size_t)MTOK * DIM / 4;
    const float4* src = (const float4*)xin;
    float4* dst = (float4*)g_x;
    for (size_t j = i; j < n4; j += (size_t)gridDim.x * blockDim.x) dst[j] = src[j];
}

// ---------------- big tiled GEMM: FFMA2 + cp.async double buffering ----------------
// C[M,N] = epi(A[M,K] @ B[K,N] + bias[N]).  M % 128 == 0, K % 16 == 0.
// grid = (ceil(N/128), M/128), 256 threads, 8x8 thread tile (as 8x4 fp32x2 pairs).
enum { EPI_NONE = 0, EPI_GELU = 1, EPI_LOSS = 3, EPI_CEN = 4 };

template <int EPI, bool FULLN>
__global__ __launch_bounds__(256, 1)
void sgemm2(const float* __restrict__ A, const float* __restrict__ B,
            const float* __restrict__ bias, float* __restrict__ Cout,
            int N, int K,
            const float* __restrict__ Xres, double* __restrict__ dAcc,
            const float* __restrict__ cohW)
{
    __shared__ __align__(16) float As[2][128 * 16];   // [stage][row*16 + k]
    __shared__ __align__(16) float Bs[2][16 * 128];   // [stage][k*128 + col]
    __shared__ float red[256];

    const int tid = threadIdx.x;
    const int tx = tid & 15;
    const int ty = tid >> 4;
    const int row0 = blockIdx.y * 128;
    const int col0 = blockIdx.x * 128;

    const int ar = tid >> 2;          // 0..63
    const int ac = (tid & 3) << 2;    // 0,4,8,12
    const int br = tid >> 4;          // 0..15
    const int bc = (tid & 15) << 3;   // 0..120

    unsigned long long acc2[32];
#pragma unroll
    for (int i = 0; i < 32; i++) acc2[i] = 0ull;

    const int NC = K >> 4;

    auto loadStage = [&](int c, int s) {
        const float* Ab = A + (size_t)row0 * K + c * 16;
        const unsigned asb = sptr(&As[s][0]);
#pragma unroll
        for (int q = 0; q < 2; q++) {
            const int r = ar + q * 64;
            cpa16(asb + (unsigned)(r * 16 + ac) * 4u, Ab + (size_t)r * K + ac);
        }
        const float* Bb = B + (size_t)(c * 16) * N;
        const unsigned bsb = sptr(&Bs[s][0]);
#pragma unroll
        for (int q = 0; q < 2; q++) {
            const int cc = bc + q * 4;
            const int gc = col0 + cc;
            if (FULLN) {
                cpa16(bsb + (unsigned)(br * 128 + cc) * 4u, Bb + (size_t)br * N + gc);
            } else {
                int rem = (N - gc) * 4;
                rem = rem < 0 ? 0 : (rem > 16 ? 16 : rem);
                const float* s2 = rem ? (Bb + (size_t)br * N + gc) : (Bb + (size_t)br * N);
                cpa16z(bsb + (unsigned)(br * 128 + cc) * 4u, s2, rem);
            }
        }
    };

    auto compute = [&](int s) {
        const float* As_ = &As[s][0];
        const float* Bs_ = &Bs[s][0];
#pragma unroll
        for (int g = 0; g < 4; g++) {
            float4 af[8];
#pragma unroll
            for (int i = 0; i < 8; i++)
                af[i] = *reinterpret_cast<const float4*>(&As_[(ty * 8 + i) * 16 + g * 4]);
#pragma unroll
            for (int j = 0; j < 4; j++) {
                const int kk = g * 4 + j;
                const float4 b0 = *reinterpret_cast<const float4*>(&Bs_[kk * 128 + tx * 8]);
                const float4 b1 = *reinterpret_cast<const float4*>(&Bs_[kk * 128 + tx * 8 + 4]);
                unsigned long long B2[4];
                B2[0] = pk(b0.x, b0.y); B2[1] = pk(b0.z, b0.w);
                B2[2] = pk(b1.x, b1.y); B2[3] = pk(b1.z, b1.w);
#pragma unroll
                for (int i = 0; i < 8; i++) {
                    const float av = (j == 0) ? af[i].x : (j == 1) ? af[i].y
                                   : (j == 2) ? af[i].z : af[i].w;
                    const unsigned long long A2 = pk(av, av);
                    ffma2(acc2[i * 4 + 0], A2, B2[0]);
                    ffma2(acc2[i * 4 + 1], A2, B2[1]);
                    ffma2(acc2[i * 4 + 2], A2, B2[2]);
                    ffma2(acc2[i * 4 + 3], A2, B2[3]);
                }
            }
        }
    };

    loadStage(0, 0);
    asm volatile("cp.async.commit_group;");
    int stage = 0;
#pragma unroll 1
    for (int c = 0; c < NC; c++) {
        if (c + 1 < NC) {
            loadStage(c + 1, stage ^ 1);
            asm volatile("cp.async.commit_group;");
            asm volatile("cp.async.wait_group 1;");
        } else {
            asm volatile("cp.async.wait_group 0;");
        }
        __syncthreads();
        compute(stage);
        __syncthreads();
        stage ^= 1;
    }

    // ---- epilogue ----
    float lsum = 0.0f, csum = 0.0f;
#pragma unroll
    for (int i = 0; i < 8; i++) {
        const int gr = row0 + ty * 8 + i;
        const bool act = (EPI == EPI_CEN) ? (g_active[gr] != 0) : false;
#pragma unroll
        for (int p = 0; p < 4; p++) {
            float v0, v1;
            upk(acc2[i * 4 + p], v0, v1);
            const int gc0 = col0 + tx * 8 + p * 2;
#pragma unroll
            for (int q = 0; q < 2; q++) {
                const int gc = gc0 + q;
                float v = (q == 0) ? v0 : v1;
                if (FULLN || gc < N) {
                    v += bias[gc];
                    if (EPI == EPI_GELU || EPI == EPI_CEN)
                        v = 0.5f * v * (1.0f + erff(v * 0.70710678118654752f));
                    if (EPI == EPI_LOSS) {
                        const float d = v - Xres[(size_t)gr * N + gc];
                        lsum += d * d;
                    } else {
                        Cout[(size_t)gr * N + gc] = v;
                        if (EPI == EPI_CEN && act) csum += v * cohW[gc];
                    }
                }
            }
        }
    }
    if (EPI == EPI_LOSS || EPI == EPI_CEN) {
        red[tid] = (EPI == EPI_LOSS) ? lsum : csum;
        __syncthreads();
        for (int s = 128; s > 0; s >>= 1) {
            if (tid < s) red[tid] += red[tid + s];
            __syncthreads();
        }
        if (tid == 0) atomicAdd(dAcc, (double)red[0]);
    }
}

// ---------------- small encoder GEMM: [M,1024] @ [1024,64] -> relu ----------------
// 64x64 tile per block, grid = M/64 = 256 blocks, 256 threads, 4x4 thread tile.
__global__ __launch_bounds__(256)
void enc_gemm(const float* __restrict__ A, const float* __restrict__ B,
              const float* __restrict__ bias, float* __restrict__ C)
{
    __shared__ __align__(16) float As[16][64];   // transposed [k][row]
    __shared__ __align__(16) float Bs[16][64];
    const int tid = threadIdx.x;
    const int tx = tid & 15, ty = tid >> 4;
    const int row0 = blockIdx.x * 64;

    const int ar = tid >> 2, acol = (tid & 3) << 2;
    const int brr = tid >> 4, bcc = (tid & 15) << 2;

    float acc[4][4];
#pragma unroll
    for (int i = 0; i < 4; i++)
#pragma unroll
        for (int j = 0; j < 4; j++) acc[i][j] = 0.0f;

    for (int k0 = 0; k0 < DIM; k0 += 16) {
        const float4 va = *reinterpret_cast<const float4*>(
            &A[(size_t)(row0 + ar) * DIM + k0 + acol]);
        As[acol + 0][ar] = va.x;
        As[acol + 1][ar] = va.y;
        As[acol + 2][ar] = va.z;
        As[acol + 3][ar] = va.w;
        *reinterpret_cast<float4*>(&Bs[brr][bcc]) =
            *reinterpret_cast<const float4*>(&B[(size_t)(k0 + brr) * SDIM + bcc]);
        __syncthreads();
#pragma unroll
        for (int kk = 0; kk < 16; kk++) {
            const float4 a4 = *reinterpret_cast<const float4*>(&As[kk][ty * 4]);
            const float4 b4 = *reinterpret_cast<const float4*>(&Bs[kk][tx * 4]);
            const float a[4] = {a4.x, a4.y, a4.z, a4.w};
            const float b[4] = {b4.x, b4.y, b4.z, b4.w};
#pragma unroll
            for (int i = 0; i < 4; i++)
#pragma unroll
                for (int j = 0; j < 4; j++)
                    acc[i][j] = fmaf(a[i], b[j], acc[i][j]);
        }
        __syncthreads();
    }
#pragma unroll
    for (int i = 0; i < 4; i++)
#pragma unroll
        for (int j = 0; j < 4; j++) {
            const int gc = tx * 4 + j;
            C[(size_t)(row0 + ty * 4 + i) * SDIM + gc] =
                fmaxf(acc[i][j] + bias[gc], 0.0f);
        }
}

// ---------------- top-K magnitude select + gated residual add ----------------
__global__ __launch_bounds__(256)
void topk_k(const float* __restrict__ H, float* __restrict__ X)
{
    const int tok = blockIdx.x;
    const int tid = threadIdx.x;

    __shared__ unsigned int hist[256];
    __shared__ unsigned int sh_prefix;
    __shared__ int sh_k;

    const float* hrow = H + (size_t)tok * DIM;
    float hv[4];
    unsigned int key[4];
#pragma unroll
    for (int i = 0; i < 4; i++) {
        hv[i] = hrow[tid + i * 256];
        key[i] = __float_as_uint(fabsf(hv[i]));
    }

    if (tid == 0) { sh_prefix = 0u; sh_k = KKEEP; }
    __syncthreads();

    for (int round = 0; round < 4; round++) {
        const int shift = 24 - round * 8;
        const unsigned int prefix = sh_prefix;
        const int kneed = sh_k;
        const unsigned int mask_hi = (round == 0) ? 0u : (0xFFFFFFFFu << (shift + 8));
        hist[tid] = 0u;
        __syncthreads();
#pragma unroll
        for (int i = 0; i < 4; i++) {
            if ((key[i] & mask_hi) == prefix)
                atomicAdd(&hist[(key[i] >> shift) & 0xFF], 1u);
        }
        __syncthreads();
        if (tid == 0) {
            int cum = 0;
            int b = 255;
            for (; b > 0; b--) {
                const int c = (int)hist[b];
                if (cum + c >= kneed) break;
                cum += c;
            }
            sh_prefix = prefix | ((unsigned int)b << shift);
            sh_k = kneed - cum;
        }
        __syncthreads();
    }
    const unsigned int kth = sh_prefix;

    if (g_active[tok]) {
        float* xrow = X + (size_t)tok * DIM;
#pragma unroll
        for (int i = 0; i < 4; i++) {
            const float add = (key[i] >= kth) ? hv[i] : 0.0f;
            xrow[tid + i * 256] += add;
        }
    }
}

// ---------------- CEN argmax + add (coh_b/denom branch-independent -> dropped) ----
__global__ void argmax_k()
{
    int b = 0;
    if (g_scores[1] > g_scores[b]) b = 1;
    if (g_scores[2] > g_scores[b]) b = 2;
    g_best = b;
}

__global__ __launch_bounds__(256)
void cen_add_k()
{
    const size_t i4 = (size_t)blockIdx.x * blockDim.x + threadIdx.x;
    const size_t tok = (i4 * 4) / DIM;
    if (!g_active[tok]) return;
    const float4* s = (const float4*)(g_sims + (size_t)g_best * MTOK * DIM);
    float4* x = (float4*)g_x;
    float4 a = x[i4];
    const float4 b = s[i4];
    a.x += b.x; a.y += b.y; a.z += b.z; a.w += b.w;
    x[i4] = a;
}

// ---------------- exit head: confidence + scatter + active update ----------------
__global__ __launch_bounds__(256)
void exit_k(const float* __restrict__ logits, float* __restrict__ out)
{
    const int tok = blockIdx.x;
    const int tid = threadIdx.x;
    if (!g_active[tok]) return;

    const float* lrow = logits + (size_t)tok * NCLS;
    __shared__ float red[256];

    float m = -INFINITY;
    for (int c = tid; c < NCLS; c += 256) m = fmaxf(m, lrow[c]);
    red[tid] = m;
    __syncthreads();
    for (int s = 128; s > 0; s >>= 1) {
        if (tid < s) red[tid] = fmaxf(red[tid], red[tid + s]);
        __syncthreads();
    }
    const float gmax = red[0];
    __syncthreads();

    float se = 0.0f;
    for (int c = tid; c < NCLS; c += 256) se += expf(lrow[c] - gmax);
    red[tid] = se;
    __syncthreads();
    for (int s = 128; s > 0; s >>= 1) {
        if (tid < s) red[tid] += red[tid + s];
        __syncthreads();
    }
    const float conf = 1.0f / red[0];

    float* orow = out + (size_t)tok * NCLS;
    for (int c = tid; c < NCLS; c += 256) orow[c] = lrow[c];

    if (tid == 0) {
        atomicAdd(&g_depth, 1ull);
        g_active[tok] = (conf < THRESH) ? 1 : 0;
    }
}

// ---------------- finalize scalars ----------------
__global__ void finalize_k(float* __restrict__ out)
{
    out[(size_t)MTOK * NCLS + 0] = (float)((double)g_depth / (double)MTOK);
    out[(size_t)MTOK * NCLS + 1] =
        (float)(g_vloss / ((double)NLAYER * (double)MTOK * (double)DIM));
}

// ---------------- host driver (graph-capturable) ----------------
extern "C" void kernel_launch(void* const* d_in, const int* in_sizes, int n_in,
                              void* d_out, int out_size)
{
    const float* x_in = (const float*)d_in[0];
    const float* dcaW = (const float*)d_in[1];
    const float* dcaB = (const float*)d_in[2];
    const float* exW  = (const float*)d_in[3];
    const float* exB  = (const float*)d_in[4];
    const float* cenW = (const float*)d_in[5];
    const float* cenB = (const float*)d_in[6];
    const float* cohW = (const float*)d_in[7];
    // d_in[8] = coh_b (unused: branch-independent for argmax)
    const float* encW = (const float*)d_in[9];
    const float* encB = (const float*)d_in[10];
    const float* decW = (const float*)d_in[11];
    const float* decB = (const float*)d_in[12];
    float* out = (float*)d_out;

    float *px, *ph, *psims, *pz, *plog;
    double *pvl, *psc;
    cudaGetSymbolAddress((void**)&px, g_x);
    cudaGetSymbolAddress((void**)&ph, g_h);
    cudaGetSymbolAddress((void**)&psims, g_sims);
    cudaGetSymbolAddress((void**)&pz, g_z);
    cudaGetSymbolAddress((void**)&plog, g_logits);
    cudaGetSymbolAddress((void**)&pvl, g_vloss);
    cudaGetSymbolAddress((void**)&psc, g_scores);

    init_k<<<4096, 256>>>(x_in);

    const dim3 blk(256);
    const dim3 grid_full(DIM / 128, MTOK / 128);                 // N=1024
    const dim3 grid_cls((NCLS + 127) / 128, MTOK / 128);         // N=1000

    for (int i = 0; i < NLAYER; i++) {
        // SparseDCA: h = gelu(x @ W + b)
        sgemm2<EPI_GELU, true><<<grid_full, blk>>>(
            px, dcaW + (size_t)i * DIM * DIM, dcaB + (size_t)i * DIM, ph,
            DIM, DIM, nullptr, nullptr, nullptr);
        topk_k<<<MTOK, 256>>>(ph, px);

        if (i == NLAYER / 2) {
            for (int n = 0; n < NBR; n++)
                sgemm2<EPI_CEN, true><<<grid_full, blk>>>(
                    px, cenW + (size_t)n * DIM * DIM, cenB + (size_t)n * DIM,
                    psims + (size_t)n * MTOK * DIM,
                    DIM, DIM, nullptr, psc + n, cohW);
            argmax_k<<<1, 1>>>();
            cen_add_k<<<(MTOK * DIM / 4) / 256, 256>>>();
        }

        // VLM: z = relu(x @ encW + encB); loss += sum((z @ decW + decB - x)^2)
        enc_gemm<<<MTOK / 64, blk>>>(px, encW, encB, pz);
        sgemm2<EPI_LOSS, true><<<grid_full, blk>>>(
            pz, decW, decB, nullptr, DIM, SDIM, px, pvl, nullptr);

        // exit head logits
        sgemm2<EPI_NONE, false><<<grid_cls, blk>>>(
            px, exW + (size_t)i * DIM * NCLS, exB + (size_t)i * NCLS, plog,
            NCLS, DIM, nullptr, nullptr, nullptr);
        exit_k<<<MTOK, 256>>>(plog, out);
    }

    finalize_k<<<1, 1>>>(out);
}